// round 1
// baseline (speedup 1.0000x reference)
#include <cuda_runtime.h>

// Problem constants
#define NUM_MODALS 4
#define SHARED_IDX 3
#define BATCH      8
#define SEQ        1024
#define CDIM       768
#define RANK       16
#define ROWS_PER_M (BATCH * SEQ)            // 8192
#define TOTAL_ROWS (NUM_MODALS * ROWS_PER_M) // 32768

// Scratch for per-modality effective weights: Weff[m][o][c]
__device__ float g_Weff[NUM_MODALS * CDIM * CDIM];

// ---------------------------------------------------------------------------
// Kernel 1: W_eff[m][o][c] = Wp[o][c] + sum_r Bw[3][o][r]*A[3][r][c]
//                                     + sum_r Bw[m][o][r]*A[m][r][c]
// ---------------------------------------------------------------------------
__global__ void weff_kernel(const float* __restrict__ Wp,
                            const float* __restrict__ A,
                            const float* __restrict__ Bw) {
    int idx = blockIdx.x * blockDim.x + threadIdx.x;
    const int total = NUM_MODALS * CDIM * CDIM;
    if (idx >= total) return;
    int c = idx % CDIM;
    int o = (idx / CDIM) % CDIM;
    int m = idx / (CDIM * CDIM);

    const float* A3 = A  + SHARED_IDX * RANK * CDIM;
    const float* B3 = Bw + SHARED_IDX * CDIM * RANK;
    const float* Am = A  + m * RANK * CDIM;
    const float* Bm = Bw + m * CDIM * RANK;

    float s = Wp[o * CDIM + c];
#pragma unroll
    for (int r = 0; r < RANK; r++) {
        s += B3[o * RANK + r] * A3[r * CDIM + c];
        s += Bm[o * RANK + r] * Am[r * CDIM + c];
    }
    g_Weff[idx] = s;
}

// ---------------------------------------------------------------------------
// Kernel 2: out[row][o] = sum_c x[row][c] * Weff[m][o][c] + bp[o]
// Classic 128x128 SMEM-tiled SGEMM, C = A * B^T form (both K-contiguous).
// 256 threads, 8x8 microtile per thread, BK=8.
// ---------------------------------------------------------------------------
#define BM 128
#define BN 128
#define BK 8
#define TM 8
#define TN 8

__global__ __launch_bounds__(256, 2)
void lora_gemm_kernel(const float* __restrict__ x,
                      const float* __restrict__ bp,
                      float* __restrict__ out) {
    __shared__ float As[BK][BM + 4];   // [k][row]
    __shared__ float Bs[BK][BN + 4];   // [k][col]

    const int tid = threadIdx.x;
    const int tx = tid % 16;           // col group
    const int ty = tid / 16;           // row group

    const int row0 = blockIdx.y * BM;  // global row base (0..32767)
    const int col0 = blockIdx.x * BN;  // output-channel base (0..767)
    const int modality = row0 / ROWS_PER_M;  // 8192 % 128 == 0 -> whole block in one modality
    const float* __restrict__ W = g_Weff + modality * CDIM * CDIM;

    // Global->SMEM load mapping: 128 rows x 8 k = 256 float4 loads; thread t
    // loads row t/2, k-quad (t%2)*4.
    const int lrow = tid >> 1;
    const int lk4  = (tid & 1) * 4;

    float acc[TM][TN];
#pragma unroll
    for (int i = 0; i < TM; i++)
#pragma unroll
        for (int j = 0; j < TN; j++) acc[i][j] = 0.f;

    const int nk = CDIM / BK;          // 96
    for (int kt = 0; kt < nk; kt++) {
        const int kbase = kt * BK;

        float4 av = *reinterpret_cast<const float4*>(
            &x[(size_t)(row0 + lrow) * CDIM + kbase + lk4]);
        float4 bv = *reinterpret_cast<const float4*>(
            &W[(size_t)(col0 + lrow) * CDIM + kbase + lk4]);

        As[lk4 + 0][lrow] = av.x;
        As[lk4 + 1][lrow] = av.y;
        As[lk4 + 2][lrow] = av.z;
        As[lk4 + 3][lrow] = av.w;
        Bs[lk4 + 0][lrow] = bv.x;
        Bs[lk4 + 1][lrow] = bv.y;
        Bs[lk4 + 2][lrow] = bv.z;
        Bs[lk4 + 3][lrow] = bv.w;
        __syncthreads();

#pragma unroll
        for (int k = 0; k < BK; k++) {
            float a[TM], b[TN];
#pragma unroll
            for (int i = 0; i < TM; i++) a[i] = As[k][ty * TM + i];
#pragma unroll
            for (int j = 0; j < TN; j++) b[j] = Bs[k][tx * TN + j];
#pragma unroll
            for (int i = 0; i < TM; i++)
#pragma unroll
                for (int j = 0; j < TN; j++)
                    acc[i][j] += a[i] * b[j];
        }
        __syncthreads();
    }

    // Epilogue: add bias, vectorized float4 stores.
#pragma unroll
    for (int i = 0; i < TM; i++) {
        const int grow = row0 + ty * TM + i;
        float* orow = out + (size_t)grow * CDIM + col0 + tx * TN;
        const float* brow = bp + col0 + tx * TN;
#pragma unroll
        for (int j4 = 0; j4 < TN; j4 += 4) {
            float4 v;
            v.x = acc[i][j4 + 0] + brow[j4 + 0];
            v.y = acc[i][j4 + 1] + brow[j4 + 1];
            v.z = acc[i][j4 + 2] + brow[j4 + 2];
            v.w = acc[i][j4 + 3] + brow[j4 + 3];
            *reinterpret_cast<float4*>(&orow[j4]) = v;
        }
    }
}

// ---------------------------------------------------------------------------
// Launch
// ---------------------------------------------------------------------------
extern "C" void kernel_launch(void* const* d_in, const int* in_sizes, int n_in,
                              void* d_out, int out_size) {
    const float* x  = (const float*)d_in[0];  // [32, 1024, 768]
    const float* Wp = (const float*)d_in[1];  // [768, 768]
    const float* bp = (const float*)d_in[2];  // [768]
    const float* A  = (const float*)d_in[3];  // [4, 16, 768]
    const float* Bw = (const float*)d_in[4];  // [4, 768, 16]
    float* out = (float*)d_out;               // [32, 1024, 768]

    // 1) Build per-modality effective weights.
    {
        const int total = NUM_MODALS * CDIM * CDIM;
        const int threads = 256;
        weff_kernel<<<(total + threads - 1) / threads, threads>>>(Wp, A, Bw);
    }

    // 2) Big GEMM: 32768 x 768 (K=768), modality-sliced B operand.
    {
        dim3 grid(CDIM / BN, TOTAL_ROWS / BM);  // (6, 256)
        lora_gemm_kernel<<<grid, 256>>>(x, bp, out);
    }
}

// round 3
// speedup vs baseline: 2.1787x; 2.1787x over previous
#include <cuda_runtime.h>
#include <cuda_bf16.h>
#include <cstdint>

// ---------------------------------------------------------------------------
// Problem constants
// ---------------------------------------------------------------------------
#define NUM_MODALS 4
#define SHARED_IDX 3
#define CDIM       768
#define RANK       16
#define ROWS_PER_M 8192
#define TOTAL_ROWS 32768

// Split-precision operand storage (device globals = allowed scratch)
__device__ __nv_bfloat16 g_Xhi[TOTAL_ROWS * CDIM];
__device__ __nv_bfloat16 g_Xlo[TOTAL_ROWS * CDIM];
__device__ __nv_bfloat16 g_Whi[NUM_MODALS * CDIM * CDIM];
__device__ __nv_bfloat16 g_Wlo[NUM_MODALS * CDIM * CDIM];

// ---------------------------------------------------------------------------
// Helpers
// ---------------------------------------------------------------------------
__device__ __forceinline__ uint32_t smem_u32(const void* p) {
    uint32_t a;
    asm("{ .reg .u64 t; cvta.to.shared.u64 t, %1; cvt.u32.u64 %0, t; }"
        : "=r"(a) : "l"(p));
    return a;
}

__device__ __forceinline__ void cp_async16(uint32_t dst, const void* src) {
    asm volatile("cp.async.cg.shared.global [%0], [%1], 16;"
                 :: "r"(dst), "l"(src) : "memory");
}
__device__ __forceinline__ void cp_commit() {
    asm volatile("cp.async.commit_group;" ::: "memory");
}
template <int N>
__device__ __forceinline__ void cp_wait() {
    asm volatile("cp.async.wait_group %0;" :: "n"(N) : "memory");
}

__device__ __forceinline__ void ldm_x4(uint32_t& r0, uint32_t& r1,
                                       uint32_t& r2, uint32_t& r3,
                                       uint32_t addr) {
    asm volatile("ldmatrix.sync.aligned.m8n8.x4.shared.b16 {%0,%1,%2,%3}, [%4];"
                 : "=r"(r0), "=r"(r1), "=r"(r2), "=r"(r3) : "r"(addr));
}

__device__ __forceinline__ void mma_bf16(float& d0, float& d1, float& d2, float& d3,
                                         uint32_t a0, uint32_t a1, uint32_t a2, uint32_t a3,
                                         uint32_t b0, uint32_t b1) {
    asm volatile("mma.sync.aligned.m16n8k16.row.col.f32.bf16.bf16.f32 "
                 "{%0,%1,%2,%3}, {%4,%5,%6,%7}, {%8,%9}, {%0,%1,%2,%3};"
                 : "+f"(d0), "+f"(d1), "+f"(d2), "+f"(d3)
                 : "r"(a0), "r"(a1), "r"(a2), "r"(a3), "r"(b0), "r"(b1));
}

// ---------------------------------------------------------------------------
// Kernel 1: split x into bf16 hi/lo (float4 vectorized)
// ---------------------------------------------------------------------------
__global__ void split_x_kernel(const float* __restrict__ x) {
    int i = blockIdx.x * blockDim.x + threadIdx.x;   // quad index
    const int nq = TOTAL_ROWS * CDIM / 4;
    if (i >= nq) return;
    float4 v = reinterpret_cast<const float4*>(x)[i];

    __nv_bfloat16 h0 = __float2bfloat16(v.x), h1 = __float2bfloat16(v.y);
    __nv_bfloat16 h2 = __float2bfloat16(v.z), h3 = __float2bfloat16(v.w);
    __nv_bfloat16 l0 = __float2bfloat16(v.x - __bfloat162float(h0));
    __nv_bfloat16 l1 = __float2bfloat16(v.y - __bfloat162float(h1));
    __nv_bfloat16 l2 = __float2bfloat16(v.z - __bfloat162float(h2));
    __nv_bfloat16 l3 = __float2bfloat16(v.w - __bfloat162float(h3));

    __nv_bfloat162* H = reinterpret_cast<__nv_bfloat162*>(g_Xhi);
    __nv_bfloat162* L = reinterpret_cast<__nv_bfloat162*>(g_Xlo);
    H[i * 2 + 0] = __nv_bfloat162(h0, h1);
    H[i * 2 + 1] = __nv_bfloat162(h2, h3);
    L[i * 2 + 0] = __nv_bfloat162(l0, l1);
    L[i * 2 + 1] = __nv_bfloat162(l2, l3);
}

// ---------------------------------------------------------------------------
// Kernel 2: W_eff = Wp + Bw3*A3 + Bwm*Am, split to bf16 hi/lo
// ---------------------------------------------------------------------------
__global__ void weff_split_kernel(const float* __restrict__ Wp,
                                  const float* __restrict__ A,
                                  const float* __restrict__ Bw) {
    int idx = blockIdx.x * blockDim.x + threadIdx.x;
    const int total = NUM_MODALS * CDIM * CDIM;
    if (idx >= total) return;
    int c = idx % CDIM;
    int o = (idx / CDIM) % CDIM;
    int m = idx / (CDIM * CDIM);

    const float* A3 = A + SHARED_IDX * RANK * CDIM;
    const float* B3 = Bw + SHARED_IDX * CDIM * RANK;
    const float* Am = A + m * RANK * CDIM;
    const float* Bm = Bw + m * CDIM * RANK;

    float s = Wp[o * CDIM + c];
#pragma unroll
    for (int r = 0; r < RANK; r++) {
        s += B3[o * RANK + r] * A3[r * CDIM + c];
        s += Bm[o * RANK + r] * Am[r * CDIM + c];
    }
    __nv_bfloat16 hi = __float2bfloat16(s);
    __nv_bfloat16 lo = __float2bfloat16(s - __bfloat162float(hi));
    g_Whi[idx] = hi;
    g_Wlo[idx] = lo;
}

// ---------------------------------------------------------------------------
// Kernel 3: bf16 split-precision GEMM via mma.sync (sm_80-generic path).
//   out[row][o] = sum_c x[row][c]*Weff[m][o][c] + bp[o]
// CTA tile 128x128, K-chunk 32 (bf16), 8 warps (2x4), warp tile 64x32.
// 3-stage cp.async pipeline. D += Ahi*Bhi + Ahi*Blo + Alo*Bhi (fp32 acc).
// ---------------------------------------------------------------------------
#define KC2    32                 // bf16 K elems per chunk
#define NCHK   (CDIM / KC2)       // 24
#define LDT    80                 // smem bytes per tile row (64 data + 16 pad)
#define OPB    (128 * LDT)        // 10240 bytes per operand tile
#define STB    (4 * OPB)          // 40960 bytes per stage (Ahi,Alo,Bhi,Blo)
#define STAGES 3
#define SMEM_TOTAL (STAGES * STB) // 122880

__device__ __forceinline__ void issue_chunk(const __nv_bfloat16* __restrict__ xhi,
                                            const __nv_bfloat16* __restrict__ xlo,
                                            const __nv_bfloat16* __restrict__ whi,
                                            const __nv_bfloat16* __restrict__ wlo,
                                            int row0, int col0, int kbase,
                                            uint32_t sstage, int tid) {
#pragma unroll
    for (int i = 0; i < 2; i++) {
        int idx = i * 256 + tid;       // 0..511
        int row = idx >> 2;            // 0..127
        int ch  = idx & 3;             // 16B chunk within 64B row
        uint32_t soff = row * LDT + ch * 16;
        size_t agoff = (size_t)(row0 + row) * CDIM + kbase + ch * 8;
        size_t bgoff = (size_t)(col0 + row) * CDIM + kbase + ch * 8;
        cp_async16(sstage + 0 * OPB + soff, xhi + agoff);
        cp_async16(sstage + 1 * OPB + soff, xlo + agoff);
        cp_async16(sstage + 2 * OPB + soff, whi + bgoff);
        cp_async16(sstage + 3 * OPB + soff, wlo + bgoff);
    }
    cp_commit();
}

__global__ __launch_bounds__(256, 1)
void lora_mma_gemm(const float* __restrict__ bp, float* __restrict__ out) {
    extern __shared__ char smem[];
    const uint32_t sbase = smem_u32(smem);
    const int tid  = threadIdx.x;
    const int wid  = tid >> 5;
    const int lane = tid & 31;
    const int warp_m = wid >> 2;       // 0..1  (64 rows each)
    const int warp_n = wid & 3;        // 0..3  (32 cols each)

    const int row0 = blockIdx.y * 128;
    const int col0 = blockIdx.x * 128;
    const int modality = row0 / ROWS_PER_M;
    const __nv_bfloat16* Whi = g_Whi + (size_t)modality * CDIM * CDIM;
    const __nv_bfloat16* Wlo = g_Wlo + (size_t)modality * CDIM * CDIM;

    float acc[4][4][4];
#pragma unroll
    for (int i = 0; i < 4; i++)
#pragma unroll
        for (int j = 0; j < 4; j++)
#pragma unroll
            for (int r = 0; r < 4; r++) acc[i][j][r] = 0.f;

    // ldmatrix lane addressing
    const int mat = lane >> 3;         // which 8x8 tile
    const int mr  = lane & 7;          // row within tile
    // A tiles: T0=(m0-7,k0-7) T1=(m8-15,k0-7) T2=(m0-7,k8-15) T3=(m8-15,k8-15)
    const int a_row = warp_m * 64 + (mat & 1) * 8 + mr;      // + i*16
    const int a_colb = (mat >> 1) * 16;                      // bytes, + kk*32
    // B tiles: T0=(n0-7,k0-7) T1=(n0-7,k8-15) T2=(n8-15,k0-7) T3=(n8-15,k8-15)
    const int b_row = warp_n * 32 + (mat >> 1) * 8 + mr;     // + jh*16
    const int b_colb = (mat & 1) * 16;                       // bytes, + kk*32

    // Prologue: 2 chunks in flight
    issue_chunk(g_Xhi, g_Xlo, Whi, Wlo, row0, col0, 0,        sbase + 0 * STB, tid);
    issue_chunk(g_Xhi, g_Xlo, Whi, Wlo, row0, col0, KC2,      sbase + 1 * STB, tid);

    for (int c = 0; c < NCHK; c++) {
        cp_wait<1>();
        __syncthreads();

        if (c + 2 < NCHK)
            issue_chunk(g_Xhi, g_Xlo, Whi, Wlo, row0, col0, (c + 2) * KC2,
                        sbase + ((c + 2) % STAGES) * STB, tid);

        const uint32_t st = sbase + (c % STAGES) * STB;
        const uint32_t aHi = st + 0 * OPB, aLo = st + 1 * OPB;
        const uint32_t bHi = st + 2 * OPB, bLo = st + 3 * OPB;

#pragma unroll
        for (int kk = 0; kk < 2; kk++) {
            uint32_t ahi[4][4], alo[4][4], bhi[4][2], blo[4][2];
#pragma unroll
            for (int i = 0; i < 4; i++) {
                uint32_t aoff = (uint32_t)(a_row + i * 16) * LDT + kk * 32 + a_colb;
                ldm_x4(ahi[i][0], ahi[i][1], ahi[i][2], ahi[i][3], aHi + aoff);
                ldm_x4(alo[i][0], alo[i][1], alo[i][2], alo[i][3], aLo + aoff);
            }
#pragma unroll
            for (int jh = 0; jh < 2; jh++) {
                uint32_t boff = (uint32_t)(b_row + jh * 16) * LDT + kk * 32 + b_colb;
                uint32_t r0, r1, r2, r3;
                ldm_x4(r0, r1, r2, r3, bHi + boff);
                bhi[2 * jh][0] = r0; bhi[2 * jh][1] = r1;
                bhi[2 * jh + 1][0] = r2; bhi[2 * jh + 1][1] = r3;
                ldm_x4(r0, r1, r2, r3, bLo + boff);
                blo[2 * jh][0] = r0; blo[2 * jh][1] = r1;
                blo[2 * jh + 1][0] = r2; blo[2 * jh + 1][1] = r3;
            }
#pragma unroll
            for (int i = 0; i < 4; i++)
#pragma unroll
                for (int j = 0; j < 4; j++) {
                    mma_bf16(acc[i][j][0], acc[i][j][1], acc[i][j][2], acc[i][j][3],
                             ahi[i][0], ahi[i][1], ahi[i][2], ahi[i][3],
                             bhi[j][0], bhi[j][1]);
                    mma_bf16(acc[i][j][0], acc[i][j][1], acc[i][j][2], acc[i][j][3],
                             ahi[i][0], ahi[i][1], ahi[i][2], ahi[i][3],
                             blo[j][0], blo[j][1]);
                    mma_bf16(acc[i][j][0], acc[i][j][1], acc[i][j][2], acc[i][j][3],
                             alo[i][0], alo[i][1], alo[i][2], alo[i][3],
                             bhi[j][0], bhi[j][1]);
                }
        }
        __syncthreads();
    }

    // Epilogue: bias + store. mma C frag: lane t -> rows (t/4, t/4+8), cols (t%4)*2..+1
    const int gID = lane >> 2;
    const int tg  = lane & 3;
#pragma unroll
    for (int j = 0; j < 4; j++) {
        const int col = col0 + warp_n * 32 + j * 8 + tg * 2;
        const float2 bb = *reinterpret_cast<const float2*>(bp + col);
#pragma unroll
        for (int i = 0; i < 4; i++) {
            const int row = row0 + warp_m * 64 + i * 16 + gID;
            float2 v0 = make_float2(acc[i][j][0] + bb.x, acc[i][j][1] + bb.y);
            float2 v1 = make_float2(acc[i][j][2] + bb.x, acc[i][j][3] + bb.y);
            *reinterpret_cast<float2*>(out + (size_t)row * CDIM + col) = v0;
            *reinterpret_cast<float2*>(out + (size_t)(row + 8) * CDIM + col) = v1;
        }
    }
}

// ---------------------------------------------------------------------------
// Launch
// ---------------------------------------------------------------------------
extern "C" void kernel_launch(void* const* d_in, const int* in_sizes, int n_in,
                              void* d_out, int out_size) {
    const float* x  = (const float*)d_in[0];  // [32, 1024, 768]
    const float* Wp = (const float*)d_in[1];  // [768, 768]
    const float* bp = (const float*)d_in[2];  // [768]
    const float* A  = (const float*)d_in[3];  // [4, 16, 768]
    const float* Bw = (const float*)d_in[4];  // [4, 768, 16]
    float* out = (float*)d_out;

    {
        const int nq = TOTAL_ROWS * CDIM / 4;
        split_x_kernel<<<(nq + 255) / 256, 256>>>(x);
    }
    {
        const int total = NUM_MODALS * CDIM * CDIM;
        weff_split_kernel<<<(total + 255) / 256, 256>>>(Wp, A, Bw);
    }
    {
        cudaFuncSetAttribute(lora_mma_gemm,
                             cudaFuncAttributeMaxDynamicSharedMemorySize, SMEM_TOTAL);
        dim3 grid(CDIM / 128, TOTAL_ROWS / 128);  // (6, 256)
        lora_mma_gemm<<<grid, 256, SMEM_TOTAL>>>(bp, out);
    }
}

// round 4
// speedup vs baseline: 2.2462x; 1.0310x over previous
#include <cuda_runtime.h>
#include <cuda_bf16.h>
#include <cstdint>

// ---------------------------------------------------------------------------
// Problem constants
// ---------------------------------------------------------------------------
#define NUM_MODALS 4
#define SHARED_IDX 3
#define CDIM       768
#define RANK       16
#define ROWS_PER_M 8192
#define TOTAL_ROWS 32768

// Split-precision operand storage (device globals = allowed scratch)
__device__ __nv_bfloat16 g_Xhi[TOTAL_ROWS * CDIM];
__device__ __nv_bfloat16 g_Xlo[TOTAL_ROWS * CDIM];
__device__ __nv_bfloat16 g_Whi[NUM_MODALS * CDIM * CDIM];
__device__ __nv_bfloat16 g_Wlo[NUM_MODALS * CDIM * CDIM];

// ---------------------------------------------------------------------------
// Helpers
// ---------------------------------------------------------------------------
__device__ __forceinline__ uint32_t smem_u32(const void* p) {
    uint32_t a;
    asm("{ .reg .u64 t; cvta.to.shared.u64 t, %1; cvt.u32.u64 %0, t; }"
        : "=r"(a) : "l"(p));
    return a;
}

__device__ __forceinline__ void cp_async16(uint32_t dst, const void* src) {
    asm volatile("cp.async.cg.shared.global [%0], [%1], 16;"
                 :: "r"(dst), "l"(src) : "memory");
}
__device__ __forceinline__ void cp_commit() {
    asm volatile("cp.async.commit_group;" ::: "memory");
}
template <int N>
__device__ __forceinline__ void cp_wait() {
    asm volatile("cp.async.wait_group %0;" :: "n"(N) : "memory");
}

__device__ __forceinline__ void ldm_x4(uint32_t& r0, uint32_t& r1,
                                       uint32_t& r2, uint32_t& r3,
                                       uint32_t addr) {
    asm volatile("ldmatrix.sync.aligned.m8n8.x4.shared.b16 {%0,%1,%2,%3}, [%4];"
                 : "=r"(r0), "=r"(r1), "=r"(r2), "=r"(r3) : "r"(addr));
}

__device__ __forceinline__ void mma_bf16(float& d0, float& d1, float& d2, float& d3,
                                         uint32_t a0, uint32_t a1, uint32_t a2, uint32_t a3,
                                         uint32_t b0, uint32_t b1) {
    asm volatile("mma.sync.aligned.m16n8k16.row.col.f32.bf16.bf16.f32 "
                 "{%0,%1,%2,%3}, {%4,%5,%6,%7}, {%8,%9}, {%0,%1,%2,%3};"
                 : "+f"(d0), "+f"(d1), "+f"(d2), "+f"(d3)
                 : "r"(a0), "r"(a1), "r"(a2), "r"(a3), "r"(b0), "r"(b1));
}

// ---------------------------------------------------------------------------
// Kernel 1: split x into bf16 hi/lo (float4 vectorized)
// ---------------------------------------------------------------------------
__global__ void split_x_kernel(const float* __restrict__ x) {
    int i = blockIdx.x * blockDim.x + threadIdx.x;   // quad index
    const int nq = TOTAL_ROWS * CDIM / 4;
    if (i >= nq) return;
    float4 v = reinterpret_cast<const float4*>(x)[i];

    __nv_bfloat16 h0 = __float2bfloat16(v.x), h1 = __float2bfloat16(v.y);
    __nv_bfloat16 h2 = __float2bfloat16(v.z), h3 = __float2bfloat16(v.w);
    __nv_bfloat16 l0 = __float2bfloat16(v.x - __bfloat162float(h0));
    __nv_bfloat16 l1 = __float2bfloat16(v.y - __bfloat162float(h1));
    __nv_bfloat16 l2 = __float2bfloat16(v.z - __bfloat162float(h2));
    __nv_bfloat16 l3 = __float2bfloat16(v.w - __bfloat162float(h3));

    __nv_bfloat162* H = reinterpret_cast<__nv_bfloat162*>(g_Xhi);
    __nv_bfloat162* L = reinterpret_cast<__nv_bfloat162*>(g_Xlo);
    H[i * 2 + 0] = __nv_bfloat162(h0, h1);
    H[i * 2 + 1] = __nv_bfloat162(h2, h3);
    L[i * 2 + 0] = __nv_bfloat162(l0, l1);
    L[i * 2 + 1] = __nv_bfloat162(l2, l3);
}

// ---------------------------------------------------------------------------
// Kernel 2: W_eff = Wp + Bw3*A3 + Bwm*Am, split to bf16 hi/lo
// ---------------------------------------------------------------------------
__global__ void weff_split_kernel(const float* __restrict__ Wp,
                                  const float* __restrict__ A,
                                  const float* __restrict__ Bw) {
    int idx = blockIdx.x * blockDim.x + threadIdx.x;
    const int total = NUM_MODALS * CDIM * CDIM;
    if (idx >= total) return;
    int c = idx % CDIM;
    int o = (idx / CDIM) % CDIM;
    int m = idx / (CDIM * CDIM);

    const float* A3 = A + SHARED_IDX * RANK * CDIM;
    const float* B3 = Bw + SHARED_IDX * CDIM * RANK;
    const float* Am = A + m * RANK * CDIM;
    const float* Bm = Bw + m * CDIM * RANK;

    float s = Wp[o * CDIM + c];
#pragma unroll
    for (int r = 0; r < RANK; r++) {
        s += B3[o * RANK + r] * A3[r * CDIM + c];
        s += Bm[o * RANK + r] * Am[r * CDIM + c];
    }
    __nv_bfloat16 hi = __float2bfloat16(s);
    __nv_bfloat16 lo = __float2bfloat16(s - __bfloat162float(hi));
    g_Whi[idx] = hi;
    g_Wlo[idx] = lo;
}

// ---------------------------------------------------------------------------
// Kernel 3: bf16 split-precision GEMM via mma.sync.
//   out[row][o] = sum_c x[row][c]*Weff[m][o][c] + bp[o]
// CTA tile 256x128, K-chunk 32 (bf16), 8 warps (2x4), warp tile 128x32.
// 3-stage cp.async pipeline, ONE __syncthreads per chunk.
// D += Ahi*Bhi + Ahi*Blo + Alo*Bhi (fp32 acc).
// ---------------------------------------------------------------------------
#define BM     256
#define KC2    32                 // bf16 K elems per chunk
#define NCHK   (CDIM / KC2)       // 24
#define LDT    80                 // smem bytes per tile row (64 data + 16 pad)
#define ATB    (BM * LDT)         // 20480 bytes per A operand tile
#define BTB    (128 * LDT)        // 10240 bytes per B operand tile
#define STB    (2 * ATB + 2 * BTB) // 61440 bytes per stage
#define OFF_AHI 0
#define OFF_ALO ATB
#define OFF_BHI (2 * ATB)
#define OFF_BLO (2 * ATB + BTB)
#define STAGES 3
#define SMEM_TOTAL (STAGES * STB) // 184320

__device__ __forceinline__ void issue_chunk(const __nv_bfloat16* __restrict__ xhi,
                                            const __nv_bfloat16* __restrict__ xlo,
                                            const __nv_bfloat16* __restrict__ whi,
                                            const __nv_bfloat16* __restrict__ wlo,
                                            int row0, int col0, int kbase,
                                            uint32_t sstage, int tid) {
    // A tiles: 256 rows x 64B = 1024 x 16B transfers per tile
#pragma unroll
    for (int i = 0; i < 4; i++) {
        int idx = i * 256 + tid;       // 0..1023
        int row = idx >> 2;            // 0..255
        int ch  = idx & 3;
        uint32_t soff = row * LDT + ch * 16;
        size_t goff = (size_t)(row0 + row) * CDIM + kbase + ch * 8;
        cp_async16(sstage + OFF_AHI + soff, xhi + goff);
        cp_async16(sstage + OFF_ALO + soff, xlo + goff);
    }
    // B tiles: 128 rows x 64B = 512 x 16B transfers per tile
#pragma unroll
    for (int i = 0; i < 2; i++) {
        int idx = i * 256 + tid;       // 0..511
        int row = idx >> 2;            // 0..127
        int ch  = idx & 3;
        uint32_t soff = row * LDT + ch * 16;
        size_t goff = (size_t)(col0 + row) * CDIM + kbase + ch * 8;
        cp_async16(sstage + OFF_BHI + soff, whi + goff);
        cp_async16(sstage + OFF_BLO + soff, wlo + goff);
    }
    cp_commit();
}

__global__ __launch_bounds__(256, 1)
void lora_mma_gemm(const float* __restrict__ bp, float* __restrict__ out) {
    extern __shared__ char smem[];
    const uint32_t sbase = smem_u32(smem);
    const int tid  = threadIdx.x;
    const int wid  = tid >> 5;
    const int lane = tid & 31;
    const int warp_m = wid >> 2;       // 0..1  (128 rows each)
    const int warp_n = wid & 3;        // 0..3  (32 cols each)

    const int row0 = blockIdx.y * BM;
    const int col0 = blockIdx.x * 128;
    const int modality = row0 / ROWS_PER_M;   // BM divides 8192
    const __nv_bfloat16* Whi = g_Whi + (size_t)modality * CDIM * CDIM;
    const __nv_bfloat16* Wlo = g_Wlo + (size_t)modality * CDIM * CDIM;

    float acc[8][4][4];
#pragma unroll
    for (int i = 0; i < 8; i++)
#pragma unroll
        for (int j = 0; j < 4; j++)
#pragma unroll
            for (int r = 0; r < 4; r++) acc[i][j][r] = 0.f;

    // ldmatrix lane addressing
    const int mat = lane >> 3;         // which 8x8 tile (0..3)
    const int mr  = lane & 7;          // row within tile
    // A frag (16x16): T0=(m0-7,k0-7) T1=(m8-15,k0-7) T2=(m0-7,k8-15) T3=(m8-15,k8-15)
    const int a_row  = warp_m * 128 + (mat & 1) * 8 + mr;    // + i*16
    const int a_colb = (mat >> 1) * 16;                      // bytes, + kk*32
    // B frag (16 cols x 16k): T0=(n0-7,k0-7) T1=(n0-7,k8-15) T2=(n8-15,k0-7) T3=(n8-15,k8-15)
    const int b_row  = warp_n * 32 + (mat >> 1) * 8 + mr;    // + jh*16
    const int b_colb = (mat & 1) * 16;                       // bytes, + kk*32

    // Prologue: 2 chunks in flight
    issue_chunk(g_Xhi, g_Xlo, Whi, Wlo, row0, col0, 0,   sbase + 0 * STB, tid);
    issue_chunk(g_Xhi, g_Xlo, Whi, Wlo, row0, col0, KC2, sbase + 1 * STB, tid);

    for (int c = 0; c < NCHK; c++) {
        cp_wait<1>();
        __syncthreads();   // also protects buffer (c-1)%3 from the issue below

        if (c + 2 < NCHK)
            issue_chunk(g_Xhi, g_Xlo, Whi, Wlo, row0, col0, (c + 2) * KC2,
                        sbase + ((c + 2) % STAGES) * STB, tid);

        const uint32_t st = sbase + (c % STAGES) * STB;
        const uint32_t aHi = st + OFF_AHI, aLo = st + OFF_ALO;
        const uint32_t bHi = st + OFF_BHI, bLo = st + OFF_BLO;

#pragma unroll
        for (int kk = 0; kk < 2; kk++) {
            // B fragments first (16 regs hi + 16 lo packed as [4][2])
            uint32_t bhi[4][2], blo[4][2];
#pragma unroll
            for (int jh = 0; jh < 2; jh++) {
                uint32_t boff = (uint32_t)(b_row + jh * 16) * LDT + kk * 32 + b_colb;
                uint32_t r0, r1, r2, r3;
                ldm_x4(r0, r1, r2, r3, bHi + boff);
                bhi[2 * jh][0] = r0; bhi[2 * jh][1] = r1;
                bhi[2 * jh + 1][0] = r2; bhi[2 * jh + 1][1] = r3;
                ldm_x4(r0, r1, r2, r3, bLo + boff);
                blo[2 * jh][0] = r0; blo[2 * jh][1] = r1;
                blo[2 * jh + 1][0] = r2; blo[2 * jh + 1][1] = r3;
            }
            // March down the 8 m-fragments, loading A just-in-time
#pragma unroll
            for (int i = 0; i < 8; i++) {
                uint32_t aoff = (uint32_t)(a_row + i * 16) * LDT + kk * 32 + a_colb;
                uint32_t ah0, ah1, ah2, ah3, al0, al1, al2, al3;
                ldm_x4(ah0, ah1, ah2, ah3, aHi + aoff);
                ldm_x4(al0, al1, al2, al3, aLo + aoff);
#pragma unroll
                for (int j = 0; j < 4; j++) {
                    mma_bf16(acc[i][j][0], acc[i][j][1], acc[i][j][2], acc[i][j][3],
                             ah0, ah1, ah2, ah3, bhi[j][0], bhi[j][1]);
                    mma_bf16(acc[i][j][0], acc[i][j][1], acc[i][j][2], acc[i][j][3],
                             ah0, ah1, ah2, ah3, blo[j][0], blo[j][1]);
                    mma_bf16(acc[i][j][0], acc[i][j][1], acc[i][j][2], acc[i][j][3],
                             al0, al1, al2, al3, bhi[j][0], bhi[j][1]);
                }
            }
        }
    }
    __syncthreads();  // last compute done before epilogue (keeps smem coherent view; cheap)

    // Epilogue: bias + store. mma C frag: lane t -> rows (t/4, t/4+8), cols (t%4)*2..+1
    const int gID = lane >> 2;
    const int tg  = lane & 3;
#pragma unroll
    for (int j = 0; j < 4; j++) {
        const int col = col0 + warp_n * 32 + j * 8 + tg * 2;
        const float2 bb = *reinterpret_cast<const float2*>(bp + col);
#pragma unroll
        for (int i = 0; i < 8; i++) {
            const int row = row0 + warp_m * 128 + i * 16 + gID;
            float2 v0 = make_float2(acc[i][j][0] + bb.x, acc[i][j][1] + bb.y);
            float2 v1 = make_float2(acc[i][j][2] + bb.x, acc[i][j][3] + bb.y);
            *reinterpret_cast<float2*>(out + (size_t)row * CDIM + col) = v0;
            *reinterpret_cast<float2*>(out + (size_t)(row + 8) * CDIM + col) = v1;
        }
    }
}

// ---------------------------------------------------------------------------
// Launch
// ---------------------------------------------------------------------------
extern "C" void kernel_launch(void* const* d_in, const int* in_sizes, int n_in,
                              void* d_out, int out_size) {
    const float* x  = (const float*)d_in[0];  // [32, 1024, 768]
    const float* Wp = (const float*)d_in[1];  // [768, 768]
    const float* bp = (const float*)d_in[2];  // [768]
    const float* A  = (const float*)d_in[3];  // [4, 16, 768]
    const float* Bw = (const float*)d_in[4];  // [4, 768, 16]
    float* out = (float*)d_out;

    {
        const int nq = TOTAL_ROWS * CDIM / 4;
        split_x_kernel<<<(nq + 255) / 256, 256>>>(x);
    }
    {
        const int total = NUM_MODALS * CDIM * CDIM;
        weff_split_kernel<<<(total + 255) / 256, 256>>>(Wp, A, Bw);
    }
    {
        cudaFuncSetAttribute(lora_mma_gemm,
                             cudaFuncAttributeMaxDynamicSharedMemorySize, SMEM_TOTAL);
        dim3 grid(CDIM / 128, TOTAL_ROWS / BM);  // (6, 128)
        lora_mma_gemm<<<grid, 256, SMEM_TOTAL>>>(bp, out);
    }
}